// round 2
// baseline (speedup 1.0000x reference)
#include <cuda_runtime.h>
#include <cstdint>

namespace {
constexpr int Bn = 16, Cn = 128, Tn = 128, Hn = 128;
constexpr int BC = Bn * Cn;
}

// Scratch (no cudaMalloc allowed): 5 MB total
__device__ float g_Ut[BC * Hn];     // clone @ W_thorn[:H] + b_thorn
__device__ float g_Uc[BC * Hn];     // clone @ W_clone[:H] + b_clone
__device__ float g_Vc[BC * Hn];     // clone @ W_clone[H:2H]
__device__ float g_thorn[BC * Hn];  // thorn_agg
__device__ float g_cagg[BC * Hn];   // clone_agg

// ---------------------------------------------------------------------------
// Precompute: out(2048x128) = clone(2048x128) @ Wsub(128x128) [+ bias]
// grid.x = 128 (16-row tiles), grid.y = 3 (which product)
// ---------------------------------------------------------------------------
__global__ __launch_bounds__(256) void precompute_kernel(
    const float* __restrict__ clone,
    const float* __restrict__ W_thorn, const float* __restrict__ b_thorn,
    const float* __restrict__ W_clone, const float* __restrict__ b_clone)
{
    const float* W;
    const float* bias;
    float* out;
    if (blockIdx.y == 0)      { W = W_thorn;         bias = b_thorn; out = g_Ut; }
    else if (blockIdx.y == 1) { W = W_clone;         bias = b_clone; out = g_Uc; }
    else                      { W = W_clone + Hn*Hn; bias = nullptr; out = g_Vc; }

    __shared__ float sA[16][32];
    __shared__ float sW[32][128];

    const int tid = threadIdx.x;
    const int tx = tid & 31;   // col group: cols tx*4 .. tx*4+3
    const int ty = tid >> 5;   // row group: rows ty*2, ty*2+1
    const int m0 = blockIdx.x * 16;

    float acc[2][4];
    #pragma unroll
    for (int r = 0; r < 2; r++)
        #pragma unroll
        for (int j = 0; j < 4; j++) acc[r][j] = 0.f;

    for (int k0 = 0; k0 < Hn; k0 += 32) {
        {   // A tile 16x32 (float2 per thread)
            int r  = tid >> 4;
            int kc = (tid & 15) * 2;
            float2 v = *reinterpret_cast<const float2*>(
                clone + (size_t)(m0 + r) * Hn + k0 + kc);
            sA[r][kc] = v.x; sA[r][kc + 1] = v.y;
        }
        #pragma unroll
        for (int i = 0; i < 4; i++) {  // W tile 32x128 (4 x float4 per thread)
            int f  = tid + 256 * i;
            int kk = f >> 5;
            int n  = (f & 31) * 4;
            float4 v = *reinterpret_cast<const float4*>(
                W + (size_t)(k0 + kk) * Hn + n);
            *reinterpret_cast<float4*>(&sW[kk][n]) = v;
        }
        __syncthreads();
        #pragma unroll
        for (int kk = 0; kk < 32; kk++) {
            float a0 = sA[ty * 2][kk];
            float a1 = sA[ty * 2 + 1][kk];
            float4 w = *reinterpret_cast<const float4*>(&sW[kk][tx * 4]);
            acc[0][0] = fmaf(a0, w.x, acc[0][0]);
            acc[0][1] = fmaf(a0, w.y, acc[0][1]);
            acc[0][2] = fmaf(a0, w.z, acc[0][2]);
            acc[0][3] = fmaf(a0, w.w, acc[0][3]);
            acc[1][0] = fmaf(a1, w.x, acc[1][0]);
            acc[1][1] = fmaf(a1, w.y, acc[1][1]);
            acc[1][2] = fmaf(a1, w.z, acc[1][2]);
            acc[1][3] = fmaf(a1, w.w, acc[1][3]);
        }
        __syncthreads();
    }

    float b0 = 0.f, b1 = 0.f, b2 = 0.f, b3 = 0.f;
    if (bias) {
        float4 bb = *reinterpret_cast<const float4*>(bias + tx * 4);
        b0 = bb.x; b1 = bb.y; b2 = bb.z; b3 = bb.w;
    }
    #pragma unroll
    for (int r = 0; r < 2; r++) {
        int row = m0 + ty * 2 + r;
        float4 o;
        o.x = acc[r][0] + b0; o.y = acc[r][1] + b1;
        o.z = acc[r][2] + b2; o.w = acc[r][3] + b3;
        *reinterpret_cast<float4*>(&out[(size_t)row * Hn + tx * 4]) = o;
    }
}

// ---------------------------------------------------------------------------
// Branch kernel: one CTA per (b,c). Y = Rel(128x128) @ W3(128x128),
// epilogue adds u (+ per-row v for clone branch), mask*relu, max over rows.
// ---------------------------------------------------------------------------
template <bool CLONE>
__global__ __launch_bounds__(256, 2) void branch_kernel(
    const float* __restrict__ rel,   // (B, C, 128, H)
    const float* __restrict__ W3,    // (H, H) row-major
    const int*   __restrict__ mask)  // (B, 128)
{
    __shared__ float sA[128][20];    // rel tile [j][k], padded
    __shared__ float sB[16][128];    // W tile  [k][n]

    const int tid = threadIdx.x;
    const int tx = tid & 15;   // cols: tx*4..+3 and 64+tx*4..+3
    const int ty = tid >> 4;   // rows: ty*4..+3 and 64+ty*4..+3
    const int bc = blockIdx.x;
    const int b  = bc >> 7;

    const float* A = rel + (size_t)bc * (Tn * Hn);

    float acc[8][8];
    #pragma unroll
    for (int i = 0; i < 8; i++)
        #pragma unroll
        for (int j = 0; j < 8; j++) acc[i][j] = 0.f;

    for (int k0 = 0; k0 < Hn; k0 += 16) {
        #pragma unroll
        for (int i = 0; i < 2; i++) {  // A tile: 128x16, float4 per thread x2
            int f  = tid + 256 * i;
            int j  = f >> 2;
            int kc = (f & 3) << 2;
            float4 v = *reinterpret_cast<const float4*>(A + (size_t)j * Hn + k0 + kc);
            *reinterpret_cast<float4*>(&sA[j][kc]) = v;
        }
        #pragma unroll
        for (int i = 0; i < 2; i++) {  // W tile: 16x128
            int f  = tid + 256 * i;
            int kk = f >> 5;
            int n  = (f & 31) << 2;
            float4 v = *reinterpret_cast<const float4*>(
                W3 + (size_t)(k0 + kk) * Hn + n);
            *reinterpret_cast<float4*>(&sB[kk][n]) = v;
        }
        __syncthreads();
        #pragma unroll
        for (int kk = 0; kk < 16; kk++) {
            float a[8], bb[8];
            #pragma unroll
            for (int i = 0; i < 4; i++) {
                a[i]     = sA[ty * 4 + i][kk];
                a[4 + i] = sA[64 + ty * 4 + i][kk];
            }
            float4 w0 = *reinterpret_cast<const float4*>(&sB[kk][tx * 4]);
            float4 w1 = *reinterpret_cast<const float4*>(&sB[kk][64 + tx * 4]);
            bb[0] = w0.x; bb[1] = w0.y; bb[2] = w0.z; bb[3] = w0.w;
            bb[4] = w1.x; bb[5] = w1.y; bb[6] = w1.z; bb[7] = w1.w;
            #pragma unroll
            for (int i = 0; i < 8; i++)
                #pragma unroll
                for (int j = 0; j < 8; j++)
                    acc[i][j] = fmaf(a[i], bb[j], acc[i][j]);
        }
        __syncthreads();
    }

    // ---- fused epilogue: add u (and v), mask*relu, column-wise max ----
    const float* U = CLONE ? g_Uc : g_Ut;
    float u[8];
    {
        float4 u0 = *reinterpret_cast<const float4*>(U + (size_t)bc * Hn + tx * 4);
        float4 u1 = *reinterpret_cast<const float4*>(U + (size_t)bc * Hn + 64 + tx * 4);
        u[0] = u0.x; u[1] = u0.y; u[2] = u0.z; u[3] = u0.w;
        u[4] = u1.x; u[5] = u1.y; u[6] = u1.z; u[7] = u1.w;
    }

    float cmax[8];
    #pragma unroll
    for (int j = 0; j < 8; j++) cmax[j] = 0.f;

    #pragma unroll
    for (int i = 0; i < 8; i++) {
        int row = (i < 4) ? (ty * 4 + i) : (64 + ty * 4 + (i - 4));
        if (mask[b * 128 + row]) {
            if (CLONE) {
                const float* vr = g_Vc + (size_t)(b * Cn + row) * Hn;
                float4 v0 = *reinterpret_cast<const float4*>(vr + tx * 4);
                float4 v1 = *reinterpret_cast<const float4*>(vr + 64 + tx * 4);
                float vv[8] = {v0.x, v0.y, v0.z, v0.w, v1.x, v1.y, v1.z, v1.w};
                #pragma unroll
                for (int j = 0; j < 8; j++) {
                    float val = acc[i][j] + u[j] + vv[j];
                    cmax[j] = fmaxf(cmax[j], fmaxf(val, 0.f));
                }
            } else {
                #pragma unroll
                for (int j = 0; j < 8; j++) {
                    float val = acc[i][j] + u[j];
                    cmax[j] = fmaxf(cmax[j], fmaxf(val, 0.f));
                }
            }
        }
    }

    __syncthreads();  // done reading sA; reuse as reduction scratch
    float (*red)[128] = reinterpret_cast<float(*)[128]>(&sA[0][0]);
    #pragma unroll
    for (int j = 0; j < 8; j++) {
        int col = (j < 4) ? (tx * 4 + j) : (64 + tx * 4 + (j - 4));
        red[ty][col] = cmax[j];
    }
    __syncthreads();
    if (tid < 128) {
        float m = 0.f;
        #pragma unroll
        for (int r = 0; r < 16; r++) m = fmaxf(m, red[r][tid]);
        float* out = CLONE ? g_cagg : g_thorn;
        out[(size_t)bc * Hn + tid] = m;
    }
}

// ---------------------------------------------------------------------------
// Final: out = clone + relu(concat(clone,food,thorn_agg,clone_agg) @ W_agg + b)
// grid.x = 128 (16-row tiles), K = 512 assembled on the fly
// ---------------------------------------------------------------------------
__global__ __launch_bounds__(256) void final_kernel(
    const float* __restrict__ clone,
    const float* __restrict__ food,
    const float* __restrict__ W_agg,   // (512, 128)
    const float* __restrict__ b_agg,
    float* __restrict__ out)
{
    __shared__ float sA[16][32];
    __shared__ float sW[32][128];

    const int tid = threadIdx.x;
    const int tx = tid & 31;
    const int ty = tid >> 5;
    const int m0 = blockIdx.x * 16;

    float acc[2][4];
    #pragma unroll
    for (int r = 0; r < 2; r++)
        #pragma unroll
        for (int j = 0; j < 4; j++) acc[r][j] = 0.f;

    for (int k0 = 0; k0 < 4 * Hn; k0 += 32) {
        const float* src;
        int s = k0 >> 7;
        if (s == 0)      src = clone;
        else if (s == 1) src = food;
        else if (s == 2) src = g_thorn;
        else             src = g_cagg;
        int kc0 = k0 & 127;
        {
            int r  = tid >> 4;
            int kc = (tid & 15) * 2;
            float2 v = *reinterpret_cast<const float2*>(
                src + (size_t)(m0 + r) * Hn + kc0 + kc);
            sA[r][kc] = v.x; sA[r][kc + 1] = v.y;
        }
        #pragma unroll
        for (int i = 0; i < 4; i++) {
            int f  = tid + 256 * i;
            int kk = f >> 5;
            int n  = (f & 31) * 4;
            float4 v = *reinterpret_cast<const float4*>(
                W_agg + (size_t)(k0 + kk) * Hn + n);
            *reinterpret_cast<float4*>(&sW[kk][n]) = v;
        }
        __syncthreads();
        #pragma unroll
        for (int kk = 0; kk < 32; kk++) {
            float a0 = sA[ty * 2][kk];
            float a1 = sA[ty * 2 + 1][kk];
            float4 w = *reinterpret_cast<const float4*>(&sW[kk][tx * 4]);
            acc[0][0] = fmaf(a0, w.x, acc[0][0]);
            acc[0][1] = fmaf(a0, w.y, acc[0][1]);
            acc[0][2] = fmaf(a0, w.z, acc[0][2]);
            acc[0][3] = fmaf(a0, w.w, acc[0][3]);
            acc[1][0] = fmaf(a1, w.x, acc[1][0]);
            acc[1][1] = fmaf(a1, w.y, acc[1][1]);
            acc[1][2] = fmaf(a1, w.z, acc[1][2]);
            acc[1][3] = fmaf(a1, w.w, acc[1][3]);
        }
        __syncthreads();
    }

    float4 bb = *reinterpret_cast<const float4*>(b_agg + tx * 4);
    #pragma unroll
    for (int r = 0; r < 2; r++) {
        int row = m0 + ty * 2 + r;
        float4 cl = *reinterpret_cast<const float4*>(
            clone + (size_t)row * Hn + tx * 4);
        float4 o;
        o.x = cl.x + fmaxf(acc[r][0] + bb.x, 0.f);
        o.y = cl.y + fmaxf(acc[r][1] + bb.y, 0.f);
        o.z = cl.z + fmaxf(acc[r][2] + bb.z, 0.f);
        o.w = cl.w + fmaxf(acc[r][3] + bb.w, 0.f);
        *reinterpret_cast<float4*>(&out[(size_t)row * Hn + tx * 4]) = o;
    }
}

// ---------------------------------------------------------------------------
extern "C" void kernel_launch(void* const* d_in, const int* in_sizes, int n_in,
                              void* d_out, int out_size)
{
    const float* food       = (const float*)d_in[0];
    const float* thorn_rel  = (const float*)d_in[1];
    const float* clone      = (const float*)d_in[2];
    const float* clone_rel  = (const float*)d_in[3];
    const int*   thorn_mask = (const int*)  d_in[4];
    const int*   clone_mask = (const int*)  d_in[5];
    const float* W_thorn    = (const float*)d_in[6];
    // d_in[7] = b_thorn (folded into precompute)
    const float* b_thorn    = (const float*)d_in[7];
    const float* W_clone    = (const float*)d_in[8];
    const float* b_clone    = (const float*)d_in[9];
    const float* W_agg      = (const float*)d_in[10];
    const float* b_agg      = (const float*)d_in[11];
    float* out = (float*)d_out;

    precompute_kernel<<<dim3(128, 3), 256>>>(clone, W_thorn, b_thorn,
                                             W_clone, b_clone);
    branch_kernel<false><<<BC, 256>>>(thorn_rel, W_thorn + Hn * Hn, thorn_mask);
    branch_kernel<true><<<BC, 256>>>(clone_rel, W_clone + 2 * Hn * Hn, clone_mask);
    final_kernel<<<128, 256>>>(clone, food, W_agg, b_agg, out);
}

// round 4
// speedup vs baseline: 2.4444x; 2.4444x over previous
#include <cuda_runtime.h>
#include <cstdint>

namespace {
constexpr int Hn = 128;
constexpr int BC = 2048;          // B*C tiles per branch
constexpr int NCTA = 148;

// dynamic SMEM layout (bytes) for persistent branch kernel
constexpr int A0_OFF  = 0;              // 128 x 132 floats
constexpr int A1_OFF  = 67584;
constexpr int B_OFF   = 135168;         // 64KB fragment image
constexpr int MSK_OFF = 200704;         // 2048 ints
constexpr int SU_OFF  = 208896;         // 2 x 128 floats
constexpr int RED_OFF = 209920;         // 4 x 128 floats
constexpr int SMEM_BYTES = 211968;
}

// device scratch (no cudaMalloc allowed)
__device__ float g_Ut[BC * Hn];
__device__ float g_Uc[BC * Hn];
__device__ float g_Vc[BC * Hn];
__device__ float g_thorn[BC * Hn];
__device__ float g_cagg[BC * Hn];
__device__ float g_Bfrag[2 * Hn * Hn];   // tf32 fragment-layout images of W2^T

// ---------------- helpers ----------------
__device__ __forceinline__ uint32_t smem_u32(const void* p) {
    uint32_t a;
    asm("{ .reg .u64 t; cvta.to.shared.u64 t, %1; cvt.u32.u64 %0, t; }"
        : "=r"(a) : "l"(p));
    return a;
}
__device__ __forceinline__ uint32_t f2tf(float f) {
    uint32_t u;
    asm("cvt.rna.tf32.f32 %0, %1;" : "=r"(u) : "f"(f));
    return u;
}
__device__ __forceinline__ void cp16(uint32_t dst, const void* src) {
    asm volatile("cp.async.cg.shared.global [%0], [%1], 16;"
                 :: "r"(dst), "l"(src) : "memory");
}
__device__ __forceinline__ void cp_commit() {
    asm volatile("cp.async.commit_group;" ::: "memory");
}
template <int N>
__device__ __forceinline__ void cp_wait() {
    asm volatile("cp.async.wait_group %0;" :: "n"(N) : "memory");
}
__device__ __forceinline__ void mma16818(float* c, uint32_t a0, uint32_t a1,
                                         uint32_t a2, uint32_t a3,
                                         uint32_t b0, uint32_t b1) {
    asm volatile(
        "mma.sync.aligned.m16n8k8.row.col.f32.tf32.tf32.f32 "
        "{%0,%1,%2,%3}, {%4,%5,%6,%7}, {%8,%9}, {%0,%1,%2,%3};"
        : "+f"(c[0]), "+f"(c[1]), "+f"(c[2]), "+f"(c[3])
        : "r"(a0), "r"(a1), "r"(a2), "r"(a3), "r"(b0), "r"(b1));
}

// ---------------------------------------------------------------------------
// Precompute Ut/Uc/Vc: 2048x128 @ 128x128 [+bias].  grid (256,3) x 256 thr.
// ---------------------------------------------------------------------------
__global__ __launch_bounds__(256) void precompute_kernel(
    const float* __restrict__ clone,
    const float* __restrict__ W_thorn, const float* __restrict__ b_thorn,
    const float* __restrict__ W_clone, const float* __restrict__ b_clone)
{
    const float* W; const float* bias; float* out;
    if (blockIdx.y == 0)      { W = W_thorn;           bias = b_thorn; out = g_Ut; }
    else if (blockIdx.y == 1) { W = W_clone;           bias = b_clone; out = g_Uc; }
    else                      { W = W_clone + Hn * Hn; bias = nullptr; out = g_Vc; }

    __shared__ float sA[8][32];
    __shared__ float sW[32][128];
    const int tid = threadIdx.x;
    const int tx = tid & 31, ty = tid >> 5;
    const int m0 = blockIdx.x * 8;

    float acc[4] = {0.f, 0.f, 0.f, 0.f};
    for (int k0 = 0; k0 < Hn; k0 += 32) {
        sA[ty][tx] = clone[(size_t)(m0 + ty) * Hn + k0 + tx];
        #pragma unroll
        for (int i = 0; i < 4; i++) {
            int f = tid + 256 * i;
            int kk = f >> 5, n = (f & 31) * 4;
            *reinterpret_cast<float4*>(&sW[kk][n]) =
                *reinterpret_cast<const float4*>(W + (size_t)(k0 + kk) * Hn + n);
        }
        __syncthreads();
        #pragma unroll
        for (int kk = 0; kk < 32; kk++) {
            float a = sA[ty][kk];
            float4 w = *reinterpret_cast<const float4*>(&sW[kk][tx * 4]);
            acc[0] = fmaf(a, w.x, acc[0]); acc[1] = fmaf(a, w.y, acc[1]);
            acc[2] = fmaf(a, w.z, acc[2]); acc[3] = fmaf(a, w.w, acc[3]);
        }
        __syncthreads();
    }
    float4 o = {acc[0], acc[1], acc[2], acc[3]};
    if (bias) {
        float4 bb = *reinterpret_cast<const float4*>(bias + tx * 4);
        o.x += bb.x; o.y += bb.y; o.z += bb.z; o.w += bb.w;
    }
    *reinterpret_cast<float4*>(&out[(size_t)(m0 + ty) * Hn + tx * 4]) = o;
}

// ---------------------------------------------------------------------------
// Build tf32 fragment-layout images of B = W2^T for both branches.
// Layout: ((ktile*16 + ntile)*32 + lane)*2 + p  holds W2[k][n] with
//   k = ktile*8 + (lane&3) + 4p,  n = ntile*8 + (lane>>2).
// ---------------------------------------------------------------------------
__global__ __launch_bounds__(256) void build_Bfrag_kernel(
    const float* __restrict__ W_thorn, const float* __restrict__ W_clone)
{
    int idx = blockIdx.x * 256 + threadIdx.x;   // 0..32767
    int seg = idx >> 14;
    int o   = idx & 16383;
    int p     = o & 1;
    int lane  = (o >> 1) & 31;
    int ntile = (o >> 6) & 15;
    int ktile = o >> 10;
    int k = ktile * 8 + (lane & 3) + 4 * p;
    int n = ntile * 8 + (lane >> 2);
    const float* Wsrc = seg ? (W_clone + 2 * Hn * Hn) : (W_thorn + Hn * Hn);
    g_Bfrag[seg * 16384 + o] = __uint_as_float(f2tf(Wsrc[(size_t)k * Hn + n]));
}

// ---------------------------------------------------------------------------
// Persistent tensor branch kernel (mma.sync tf32)
// ---------------------------------------------------------------------------
__device__ __forceinline__ void load_tile(const float* __restrict__ rel,
                                          const float* __restrict__ U,
                                          int tile, int slot, uint32_t sb)
{
    const int tid = threadIdx.x;
    const float* src = rel + (size_t)tile * 16384;
    const uint32_t abase = sb + (slot ? A1_OFF : A0_OFF);
    #pragma unroll
    for (int c = 0; c < 16; c++) {
        int j = tid + 256 * c;
        int row = j >> 5, q = j & 31;
        cp16(abase + row * 528 + q * 16, src + (size_t)j * 4);
    }
    if (tid < 32)
        cp16(sb + SU_OFF + slot * 512 + tid * 16, U + (size_t)tile * 128 + tid * 4);
}

template <bool CLONE>
__device__ __forceinline__ void tile_process(int tile, int slot, char* smem,
                                             float* __restrict__ outp)
{
    const int tid = threadIdx.x, lane = tid & 31, wid = tid >> 5;
    const int wm = wid >> 1, wn = wid & 1;
    const int g = lane >> 2, t = lane & 3;
    const int b = tile >> 7;
    const float* As    = reinterpret_cast<const float*>(smem + (slot ? A1_OFF : A0_OFF));
    const float* sB    = reinterpret_cast<const float*>(smem + B_OFF);
    const int*   smask = reinterpret_cast<const int*>(smem + MSK_OFF);
    const float* su    = reinterpret_cast<const float*>(smem + SU_OFF + slot * 512);
    float*       red   = reinterpret_cast<float*>(smem + RED_OFF);

    float acc[2][8][4];
    #pragma unroll
    for (int mt = 0; mt < 2; mt++)
        #pragma unroll
        for (int nt = 0; nt < 8; nt++)
            #pragma unroll
            for (int j = 0; j < 4; j++) acc[mt][nt][j] = 0.f;

    #pragma unroll 4
    for (int kt = 0; kt < 16; kt++) {
        uint2 bf[8];
        #pragma unroll
        for (int nt = 0; nt < 8; nt++)
            bf[nt] = *reinterpret_cast<const uint2*>(
                sB + (size_t)(((kt * 16) + wn * 8 + nt) * 32 + lane) * 2);
        #pragma unroll
        for (int mt = 0; mt < 2; mt++) {
            const float* ar = As + (wm * 32 + mt * 16 + g) * 132 + kt * 8 + t;
            uint32_t a0 = f2tf(ar[0]);
            uint32_t a2 = f2tf(ar[4]);
            uint32_t a1 = f2tf(ar[8 * 132]);
            uint32_t a3 = f2tf(ar[8 * 132 + 4]);
            #pragma unroll
            for (int nt = 0; nt < 8; nt++)
                mma16818(acc[mt][nt], a0, a1, a2, a3, bf[nt].x, bf[nt].y);
        }
    }

    // fused epilogue: +u (+v), mask*relu, column max over 128 rows
    float cmax[8][2];
    #pragma unroll
    for (int nt = 0; nt < 8; nt++) { cmax[nt][0] = 0.f; cmax[nt][1] = 0.f; }

    const float* vb = CLONE ? (g_Vc + (size_t)b * 16384) : nullptr;
    #pragma unroll
    for (int mt = 0; mt < 2; mt++) {
        int r0 = wm * 32 + mt * 16 + g;
        int m0 = smask[b * 128 + r0];
        int m1 = smask[b * 128 + r0 + 8];
        #pragma unroll
        for (int nt = 0; nt < 8; nt++) {
            int c0 = wn * 64 + nt * 8 + t * 2;
            float2 uu = *reinterpret_cast<const float2*>(su + c0);
            float2 v0 = {0.f, 0.f}, v1 = {0.f, 0.f};
            if (CLONE) {
                v0 = *reinterpret_cast<const float2*>(vb + (size_t)r0 * 128 + c0);
                v1 = *reinterpret_cast<const float2*>(vb + (size_t)(r0 + 8) * 128 + c0);
            }
            float x0 = acc[mt][nt][0] + uu.x + v0.x;
            float x1 = acc[mt][nt][1] + uu.y + v0.y;
            float x2 = acc[mt][nt][2] + uu.x + v1.x;
            float x3 = acc[mt][nt][3] + uu.y + v1.y;
            x0 = m0 ? fmaxf(x0, 0.f) : 0.f;
            x1 = m0 ? fmaxf(x1, 0.f) : 0.f;
            x2 = m1 ? fmaxf(x2, 0.f) : 0.f;
            x3 = m1 ? fmaxf(x3, 0.f) : 0.f;
            cmax[nt][0] = fmaxf(cmax[nt][0], fmaxf(x0, x2));
            cmax[nt][1] = fmaxf(cmax[nt][1], fmaxf(x1, x3));
        }
    }
    #pragma unroll
    for (int nt = 0; nt < 8; nt++)
        #pragma unroll
        for (int j2 = 0; j2 < 2; j2++) {
            float v = cmax[nt][j2];
            v = fmaxf(v, __shfl_xor_sync(0xFFFFFFFFu, v, 4));
            v = fmaxf(v, __shfl_xor_sync(0xFFFFFFFFu, v, 8));
            v = fmaxf(v, __shfl_xor_sync(0xFFFFFFFFu, v, 16));
            cmax[nt][j2] = v;
        }
    if (g == 0) {
        #pragma unroll
        for (int nt = 0; nt < 8; nt++) {
            int c0 = wn * 64 + nt * 8 + t * 2;
            red[wm * 128 + c0]     = cmax[nt][0];
            red[wm * 128 + c0 + 1] = cmax[nt][1];
        }
    }
    __syncthreads();
    if (tid < 128) {
        float m = fmaxf(fmaxf(red[tid], red[128 + tid]),
                        fmaxf(red[256 + tid], red[384 + tid]));
        outp[(size_t)tile * 128 + tid] = m;
    }
}

template <bool CLONE>
__device__ void run_segment(const float* __restrict__ rel,
                            const float* __restrict__ Bimg,
                            const float* __restrict__ U,
                            const int*   __restrict__ maskg,
                            float* __restrict__ outp, char* smem)
{
    const int tid = threadIdx.x;
    const uint32_t sb = smem_u32(smem);

    // B fragment image + segment mask (one group)
    for (int j = tid; j < 4096; j += 256)
        cp16(sb + B_OFF + j * 16, Bimg + (size_t)j * 4);
    for (int j = tid; j < 512; j += 256)
        cp16(sb + MSK_OFF + j * 16, maskg + (size_t)j * 4);
    cp_commit();

    const int i0 = blockIdx.x;
    load_tile(rel, U, i0, 0, sb);
    cp_commit();

    int w = 0;
    for (int i = i0; i < BC; i += NCTA, w ^= 1) {
        int nx = i + NCTA;
        if (nx < BC) {
            load_tile(rel, U, nx, w ^ 1, sb);
            cp_commit();
            cp_wait<1>();
        } else {
            cp_wait<0>();
        }
        __syncthreads();
        tile_process<CLONE>(i, w, smem, outp);
        __syncthreads();
    }
}

__global__ __launch_bounds__(256, 1) void branch_persist_kernel(
    const float* __restrict__ thorn_rel, const float* __restrict__ clone_rel,
    const int* __restrict__ thorn_mask,  const int* __restrict__ clone_mask)
{
    extern __shared__ __align__(16) char smem[];
    run_segment<false>(thorn_rel, g_Bfrag,         g_Ut, thorn_mask, g_thorn, smem);
    __syncthreads();
    run_segment<true >(clone_rel, g_Bfrag + 16384, g_Uc, clone_mask, g_cagg, smem);
}

// ---------------------------------------------------------------------------
// Final: out = clone + relu(concat(clone,food,thorn,cagg) @ W_agg + b)
// ---------------------------------------------------------------------------
__global__ __launch_bounds__(256) void final_kernel(
    const float* __restrict__ clone,
    const float* __restrict__ food,
    const float* __restrict__ W_agg,
    const float* __restrict__ b_agg,
    float* __restrict__ out)
{
    __shared__ float sA[8][32];
    __shared__ float sW[32][128];
    const int tid = threadIdx.x;
    const int tx = tid & 31, ty = tid >> 5;
    const int m0 = blockIdx.x * 8;

    float acc[4] = {0.f, 0.f, 0.f, 0.f};
    for (int k0 = 0; k0 < 4 * Hn; k0 += 32) {
        const float* src;
        int s = k0 >> 7;
        if (s == 0)      src = clone;
        else if (s == 1) src = food;
        else if (s == 2) src = g_thorn;
        else             src = g_cagg;
        sA[ty][tx] = src[(size_t)(m0 + ty) * Hn + (k0 & 127) + tx];
        #pragma unroll
        for (int i = 0; i < 4; i++) {
            int f = tid + 256 * i;
            int kk = f >> 5, n = (f & 31) * 4;
            *reinterpret_cast<float4*>(&sW[kk][n]) =
                *reinterpret_cast<const float4*>(W_agg + (size_t)(k0 + kk) * Hn + n);
        }
        __syncthreads();
        #pragma unroll
        for (int kk = 0; kk < 32; kk++) {
            float a = sA[ty][kk];
            float4 w = *reinterpret_cast<const float4*>(&sW[kk][tx * 4]);
            acc[0] = fmaf(a, w.x, acc[0]); acc[1] = fmaf(a, w.y, acc[1]);
            acc[2] = fmaf(a, w.z, acc[2]); acc[3] = fmaf(a, w.w, acc[3]);
        }
        __syncthreads();
    }
    float4 bb = *reinterpret_cast<const float4*>(b_agg + tx * 4);
    int rw = m0 + ty;
    float4 cl = *reinterpret_cast<const float4*>(clone + (size_t)rw * Hn + tx * 4);
    float4 o;
    o.x = cl.x + fmaxf(acc[0] + bb.x, 0.f);
    o.y = cl.y + fmaxf(acc[1] + bb.y, 0.f);
    o.z = cl.z + fmaxf(acc[2] + bb.z, 0.f);
    o.w = cl.w + fmaxf(acc[3] + bb.w, 0.f);
    *reinterpret_cast<float4*>(&out[(size_t)rw * Hn + tx * 4]) = o;
}

// ---------------------------------------------------------------------------
extern "C" void kernel_launch(void* const* d_in, const int* in_sizes, int n_in,
                              void* d_out, int out_size)
{
    const float* food       = (const float*)d_in[0];
    const float* thorn_rel  = (const float*)d_in[1];
    const float* clone      = (const float*)d_in[2];
    const float* clone_rel  = (const float*)d_in[3];
    const int*   thorn_mask = (const int*)  d_in[4];
    const int*   clone_mask = (const int*)  d_in[5];
    const float* W_thorn    = (const float*)d_in[6];
    const float* b_thorn    = (const float*)d_in[7];
    const float* W_clone    = (const float*)d_in[8];
    const float* b_clone    = (const float*)d_in[9];
    const float* W_agg      = (const float*)d_in[10];
    const float* b_agg      = (const float*)d_in[11];
    float* out = (float*)d_out;

    static bool attr_done = false;
    if (!attr_done) {
        cudaFuncSetAttribute(branch_persist_kernel,
                             cudaFuncAttributeMaxDynamicSharedMemorySize, SMEM_BYTES);
        attr_done = true;
    }

    precompute_kernel<<<dim3(256, 3), 256>>>(clone, W_thorn, b_thorn,
                                             W_clone, b_clone);
    build_Bfrag_kernel<<<128, 256>>>(W_thorn, W_clone);
    branch_persist_kernel<<<NCTA, 256, SMEM_BYTES>>>(thorn_rel, clone_rel,
                                                     thorn_mask, clone_mask);
    final_kernel<<<256, 256>>>(clone, food, W_agg, b_agg, out);
}

// round 5
// speedup vs baseline: 2.4460x; 1.0007x over previous
#include <cuda_runtime.h>
#include <cstdint>

namespace {
constexpr int Hn = 128;
constexpr int BC = 2048;          // B*C tiles per branch
constexpr int NCTA = 148;

// dynamic SMEM layout (bytes) for persistent branch kernel
constexpr int A0_OFF  = 0;              // 128 x 132 floats
constexpr int A1_OFF  = 67584;
constexpr int B_OFF   = 135168;         // 64KB fragment image
constexpr int MSK_OFF = 200704;         // 2048 ints
constexpr int SU_OFF  = 208896;         // 2 x 128 floats
constexpr int RED_OFF = 209920;         // 4 x 128 floats
constexpr int SMEM_BYTES = 211968;
}

// device scratch (no cudaMalloc allowed)
__device__ float g_Ut[BC * Hn];
__device__ float g_Uc[BC * Hn];
__device__ float g_Vc[BC * Hn];
__device__ float g_thorn[BC * Hn];
__device__ float g_cagg[BC * Hn];
__device__ float g_Bfrag[2 * Hn * Hn];   // tf32 fragment-layout images of W2^T

// ---------------- helpers ----------------
__device__ __forceinline__ uint32_t smem_u32(const void* p) {
    uint32_t a;
    asm("{ .reg .u64 t; cvta.to.shared.u64 t, %1; cvt.u32.u64 %0, t; }"
        : "=r"(a) : "l"(p));
    return a;
}
__device__ __forceinline__ uint32_t f2tf(float f) {
    uint32_t u;
    asm("cvt.rna.tf32.f32 %0, %1;" : "=r"(u) : "f"(f));
    return u;
}
__device__ __forceinline__ void cp16(uint32_t dst, const void* src) {
    asm volatile("cp.async.cg.shared.global [%0], [%1], 16;"
                 :: "r"(dst), "l"(src) : "memory");
}
__device__ __forceinline__ void cp_commit() {
    asm volatile("cp.async.commit_group;" ::: "memory");
}
template <int N>
__device__ __forceinline__ void cp_wait() {
    asm volatile("cp.async.wait_group %0;" :: "n"(N) : "memory");
}
__device__ __forceinline__ void mma16818(float* c, uint32_t a0, uint32_t a1,
                                         uint32_t a2, uint32_t a3,
                                         uint32_t b0, uint32_t b1) {
    asm volatile(
        "mma.sync.aligned.m16n8k8.row.col.f32.tf32.tf32.f32 "
        "{%0,%1,%2,%3}, {%4,%5,%6,%7}, {%8,%9}, {%0,%1,%2,%3};"
        : "+f"(c[0]), "+f"(c[1]), "+f"(c[2]), "+f"(c[3])
        : "r"(a0), "r"(a1), "r"(a2), "r"(a3), "r"(b0), "r"(b1));
}

// ---------------------------------------------------------------------------
// Precompute Ut/Uc/Vc: 2048x128 @ 128x128 [+bias].  grid (256,3) x 256 thr.
// ---------------------------------------------------------------------------
__global__ __launch_bounds__(256) void precompute_kernel(
    const float* __restrict__ clone,
    const float* __restrict__ W_thorn, const float* __restrict__ b_thorn,
    const float* __restrict__ W_clone, const float* __restrict__ b_clone)
{
    const float* W; const float* bias; float* out;
    if (blockIdx.y == 0)      { W = W_thorn;           bias = b_thorn; out = g_Ut; }
    else if (blockIdx.y == 1) { W = W_clone;           bias = b_clone; out = g_Uc; }
    else                      { W = W_clone + Hn * Hn; bias = nullptr; out = g_Vc; }

    __shared__ float sA[8][32];
    __shared__ float sW[32][128];
    const int tid = threadIdx.x;
    const int tx = tid & 31, ty = tid >> 5;
    const int m0 = blockIdx.x * 8;

    float acc[4] = {0.f, 0.f, 0.f, 0.f};
    for (int k0 = 0; k0 < Hn; k0 += 32) {
        sA[ty][tx] = clone[(size_t)(m0 + ty) * Hn + k0 + tx];
        #pragma unroll
        for (int i = 0; i < 4; i++) {
            int f = tid + 256 * i;
            int kk = f >> 5, n = (f & 31) * 4;
            *reinterpret_cast<float4*>(&sW[kk][n]) =
                *reinterpret_cast<const float4*>(W + (size_t)(k0 + kk) * Hn + n);
        }
        __syncthreads();
        #pragma unroll
        for (int kk = 0; kk < 32; kk++) {
            float a = sA[ty][kk];
            float4 w = *reinterpret_cast<const float4*>(&sW[kk][tx * 4]);
            acc[0] = fmaf(a, w.x, acc[0]); acc[1] = fmaf(a, w.y, acc[1]);
            acc[2] = fmaf(a, w.z, acc[2]); acc[3] = fmaf(a, w.w, acc[3]);
        }
        __syncthreads();
    }
    float4 o = {acc[0], acc[1], acc[2], acc[3]};
    if (bias) {
        float4 bb = *reinterpret_cast<const float4*>(bias + tx * 4);
        o.x += bb.x; o.y += bb.y; o.z += bb.z; o.w += bb.w;
    }
    *reinterpret_cast<float4*>(&out[(size_t)(m0 + ty) * Hn + tx * 4]) = o;
}

// ---------------------------------------------------------------------------
// Build tf32 fragment-layout images of B = W2^T for both branches.
// Layout: ((ktile*16 + ntile)*32 + lane)*2 + p  holds W2[k][n] with
//   k = ktile*8 + (lane&3) + 4p,  n = ntile*8 + (lane>>2).
// ---------------------------------------------------------------------------
__global__ __launch_bounds__(256) void build_Bfrag_kernel(
    const float* __restrict__ W_thorn, const float* __restrict__ W_clone)
{
    int idx = blockIdx.x * 256 + threadIdx.x;   // 0..32767
    int seg = idx >> 14;
    int o   = idx & 16383;
    int p     = o & 1;
    int lane  = (o >> 1) & 31;
    int ntile = (o >> 6) & 15;
    int ktile = o >> 10;
    int k = ktile * 8 + (lane & 3) + 4 * p;
    int n = ntile * 8 + (lane >> 2);
    const float* Wsrc = seg ? (W_clone + 2 * Hn * Hn) : (W_thorn + Hn * Hn);
    g_Bfrag[seg * 16384 + o] = __uint_as_float(f2tf(Wsrc[(size_t)k * Hn + n]));
}

// ---------------------------------------------------------------------------
// Persistent tensor branch kernel (mma.sync tf32)
// ---------------------------------------------------------------------------
__device__ __forceinline__ void load_tile(const float* __restrict__ rel,
                                          const float* __restrict__ U,
                                          int tile, int slot, uint32_t sb)
{
    const int tid = threadIdx.x;
    const float* src = rel + (size_t)tile * 16384;
    const uint32_t abase = sb + (slot ? A1_OFF : A0_OFF);
    #pragma unroll
    for (int c = 0; c < 16; c++) {
        int j = tid + 256 * c;
        int row = j >> 5, q = j & 31;
        cp16(abase + row * 528 + q * 16, src + (size_t)j * 4);
    }
    if (tid < 32)
        cp16(sb + SU_OFF + slot * 512 + tid * 16, U + (size_t)tile * 128 + tid * 4);
}

template <bool CLONE>
__device__ __forceinline__ void tile_process(int tile, int slot, char* smem,
                                             float* __restrict__ outp)
{
    const int tid = threadIdx.x, lane = tid & 31, wid = tid >> 5;
    const int wm = wid >> 1, wn = wid & 1;
    const int g = lane >> 2, t = lane & 3;
    const int b = tile >> 7;
    const float* As    = reinterpret_cast<const float*>(smem + (slot ? A1_OFF : A0_OFF));
    const float* sB    = reinterpret_cast<const float*>(smem + B_OFF);
    const int*   smask = reinterpret_cast<const int*>(smem + MSK_OFF);
    const float* su    = reinterpret_cast<const float*>(smem + SU_OFF + slot * 512);
    float*       red   = reinterpret_cast<float*>(smem + RED_OFF);

    float acc[2][8][4];
    #pragma unroll
    for (int mt = 0; mt < 2; mt++)
        #pragma unroll
        for (int nt = 0; nt < 8; nt++)
            #pragma unroll
            for (int j = 0; j < 4; j++) acc[mt][nt][j] = 0.f;

    #pragma unroll 4
    for (int kt = 0; kt < 16; kt++) {
        uint2 bf[8];
        #pragma unroll
        for (int nt = 0; nt < 8; nt++)
            bf[nt] = *reinterpret_cast<const uint2*>(
                sB + (size_t)(((kt * 16) + wn * 8 + nt) * 32 + lane) * 2);
        #pragma unroll
        for (int mt = 0; mt < 2; mt++) {
            const float* ar = As + (wm * 32 + mt * 16 + g) * 132 + kt * 8 + t;
            uint32_t a0 = f2tf(ar[0]);
            uint32_t a2 = f2tf(ar[4]);
            uint32_t a1 = f2tf(ar[8 * 132]);
            uint32_t a3 = f2tf(ar[8 * 132 + 4]);
            #pragma unroll
            for (int nt = 0; nt < 8; nt++)
                mma16818(acc[mt][nt], a0, a1, a2, a3, bf[nt].x, bf[nt].y);
        }
    }

    // fused epilogue: +u (+v), mask*relu, column max over 128 rows
    float cmax[8][2];
    #pragma unroll
    for (int nt = 0; nt < 8; nt++) { cmax[nt][0] = 0.f; cmax[nt][1] = 0.f; }

    const float* vb = CLONE ? (g_Vc + (size_t)b * 16384) : nullptr;
    #pragma unroll
    for (int mt = 0; mt < 2; mt++) {
        int r0 = wm * 32 + mt * 16 + g;
        int m0 = smask[b * 128 + r0];
        int m1 = smask[b * 128 + r0 + 8];
        #pragma unroll
        for (int nt = 0; nt < 8; nt++) {
            int c0 = wn * 64 + nt * 8 + t * 2;
            float2 uu = *reinterpret_cast<const float2*>(su + c0);
            float2 v0 = {0.f, 0.f}, v1 = {0.f, 0.f};
            if (CLONE) {
                v0 = *reinterpret_cast<const float2*>(vb + (size_t)r0 * 128 + c0);
                v1 = *reinterpret_cast<const float2*>(vb + (size_t)(r0 + 8) * 128 + c0);
            }
            float x0 = acc[mt][nt][0] + uu.x + v0.x;
            float x1 = acc[mt][nt][1] + uu.y + v0.y;
            float x2 = acc[mt][nt][2] + uu.x + v1.x;
            float x3 = acc[mt][nt][3] + uu.y + v1.y;
            x0 = m0 ? fmaxf(x0, 0.f) : 0.f;
            x1 = m0 ? fmaxf(x1, 0.f) : 0.f;
            x2 = m1 ? fmaxf(x2, 0.f) : 0.f;
            x3 = m1 ? fmaxf(x3, 0.f) : 0.f;
            cmax[nt][0] = fmaxf(cmax[nt][0], fmaxf(x0, x2));
            cmax[nt][1] = fmaxf(cmax[nt][1], fmaxf(x1, x3));
        }
    }
    #pragma unroll
    for (int nt = 0; nt < 8; nt++)
        #pragma unroll
        for (int j2 = 0; j2 < 2; j2++) {
            float v = cmax[nt][j2];
            v = fmaxf(v, __shfl_xor_sync(0xFFFFFFFFu, v, 4));
            v = fmaxf(v, __shfl_xor_sync(0xFFFFFFFFu, v, 8));
            v = fmaxf(v, __shfl_xor_sync(0xFFFFFFFFu, v, 16));
            cmax[nt][j2] = v;
        }
    if (g == 0) {
        #pragma unroll
        for (int nt = 0; nt < 8; nt++) {
            int c0 = wn * 64 + nt * 8 + t * 2;
            red[wm * 128 + c0]     = cmax[nt][0];
            red[wm * 128 + c0 + 1] = cmax[nt][1];
        }
    }
    __syncthreads();
    if (tid < 128) {
        float m = fmaxf(fmaxf(red[tid], red[128 + tid]),
                        fmaxf(red[256 + tid], red[384 + tid]));
        outp[(size_t)tile * 128 + tid] = m;
    }
}

template <bool CLONE>
__device__ void run_segment(const float* __restrict__ rel,
                            const float* __restrict__ Bimg,
                            const float* __restrict__ U,
                            const int*   __restrict__ maskg,
                            float* __restrict__ outp, char* smem)
{
    const int tid = threadIdx.x;
    const uint32_t sb = smem_u32(smem);

    // B fragment image + segment mask (one group)
    for (int j = tid; j < 4096; j += 256)
        cp16(sb + B_OFF + j * 16, Bimg + (size_t)j * 4);
    for (int j = tid; j < 512; j += 256)
        cp16(sb + MSK_OFF + j * 16, maskg + (size_t)j * 4);
    cp_commit();

    const int i0 = blockIdx.x;
    load_tile(rel, U, i0, 0, sb);
    cp_commit();

    int w = 0;
    for (int i = i0; i < BC; i += NCTA, w ^= 1) {
        int nx = i + NCTA;
        if (nx < BC) {
            load_tile(rel, U, nx, w ^ 1, sb);
            cp_commit();
            cp_wait<1>();
        } else {
            cp_wait<0>();
        }
        __syncthreads();
        tile_process<CLONE>(i, w, smem, outp);
        __syncthreads();
    }
}

__global__ __launch_bounds__(256, 1) void branch_persist_kernel(
    const float* __restrict__ thorn_rel, const float* __restrict__ clone_rel,
    const int* __restrict__ thorn_mask,  const int* __restrict__ clone_mask)
{
    extern __shared__ __align__(16) char smem[];
    run_segment<false>(thorn_rel, g_Bfrag,         g_Ut, thorn_mask, g_thorn, smem);
    __syncthreads();
    run_segment<true >(clone_rel, g_Bfrag + 16384, g_Uc, clone_mask, g_cagg, smem);
}

// ---------------------------------------------------------------------------
// Final: out = clone + relu(concat(clone,food,thorn,cagg) @ W_agg + b)
// ---------------------------------------------------------------------------
__global__ __launch_bounds__(256) void final_kernel(
    const float* __restrict__ clone,
    const float* __restrict__ food,
    const float* __restrict__ W_agg,
    const float* __restrict__ b_agg,
    float* __restrict__ out)
{
    __shared__ float sA[8][32];
    __shared__ float sW[32][128];
    const int tid = threadIdx.x;
    const int tx = tid & 31, ty = tid >> 5;
    const int m0 = blockIdx.x * 8;

    float acc[4] = {0.f, 0.f, 0.f, 0.f};
    for (int k0 = 0; k0 < 4 * Hn; k0 += 32) {
        const float* src;
        int s = k0 >> 7;
        if (s == 0)      src = clone;
        else if (s == 1) src = food;
        else if (s == 2) src = g_thorn;
        else             src = g_cagg;
        sA[ty][tx] = src[(size_t)(m0 + ty) * Hn + (k0 & 127) + tx];
        #pragma unroll
        for (int i = 0; i < 4; i++) {
            int f = tid + 256 * i;
            int kk = f >> 5, n = (f & 31) * 4;
            *reinterpret_cast<float4*>(&sW[kk][n]) =
                *reinterpret_cast<const float4*>(W_agg + (size_t)(k0 + kk) * Hn + n);
        }
        __syncthreads();
        #pragma unroll
        for (int kk = 0; kk < 32; kk++) {
            float a = sA[ty][kk];
            float4 w = *reinterpret_cast<const float4*>(&sW[kk][tx * 4]);
            acc[0] = fmaf(a, w.x, acc[0]); acc[1] = fmaf(a, w.y, acc[1]);
            acc[2] = fmaf(a, w.z, acc[2]); acc[3] = fmaf(a, w.w, acc[3]);
        }
        __syncthreads();
    }
    float4 bb = *reinterpret_cast<const float4*>(b_agg + tx * 4);
    int rw = m0 + ty;
    float4 cl = *reinterpret_cast<const float4*>(clone + (size_t)rw * Hn + tx * 4);
    float4 o;
    o.x = cl.x + fmaxf(acc[0] + bb.x, 0.f);
    o.y = cl.y + fmaxf(acc[1] + bb.y, 0.f);
    o.z = cl.z + fmaxf(acc[2] + bb.z, 0.f);
    o.w = cl.w + fmaxf(acc[3] + bb.w, 0.f);
    *reinterpret_cast<float4*>(&out[(size_t)rw * Hn + tx * 4]) = o;
}

// ---------------------------------------------------------------------------
extern "C" void kernel_launch(void* const* d_in, const int* in_sizes, int n_in,
                              void* d_out, int out_size)
{
    const float* food       = (const float*)d_in[0];
    const float* thorn_rel  = (const float*)d_in[1];
    const float* clone      = (const float*)d_in[2];
    const float* clone_rel  = (const float*)d_in[3];
    const int*   thorn_mask = (const int*)  d_in[4];
    const int*   clone_mask = (const int*)  d_in[5];
    const float* W_thorn    = (const float*)d_in[6];
    const float* b_thorn    = (const float*)d_in[7];
    const float* W_clone    = (const float*)d_in[8];
    const float* b_clone    = (const float*)d_in[9];
    const float* W_agg      = (const float*)d_in[10];
    const float* b_agg      = (const float*)d_in[11];
    float* out = (float*)d_out;

    static bool attr_done = false;
    if (!attr_done) {
        cudaFuncSetAttribute(branch_persist_kernel,
                             cudaFuncAttributeMaxDynamicSharedMemorySize, SMEM_BYTES);
        attr_done = true;
    }

    precompute_kernel<<<dim3(256, 3), 256>>>(clone, W_thorn, b_thorn,
                                             W_clone, b_clone);
    build_Bfrag_kernel<<<128, 256>>>(W_thorn, W_clone);
    branch_persist_kernel<<<NCTA, 256, SMEM_BYTES>>>(thorn_rel, clone_rel,
                                                     thorn_mask, clone_mask);
    final_kernel<<<256, 256>>>(clone, food, W_agg, b_agg, out);
}

// round 6
// speedup vs baseline: 2.4464x; 1.0002x over previous
#include <cuda_runtime.h>
#include <cstdint>

namespace {
constexpr int Hn = 128;
constexpr int BC = 2048;          // B*C tiles per branch
constexpr int NCTA = 148;

// dynamic SMEM layout (bytes) for persistent branch kernel
constexpr int A0_OFF  = 0;              // 128 x 132 floats
constexpr int A1_OFF  = 67584;
constexpr int B_OFF   = 135168;         // 64KB fragment image
constexpr int MSK_OFF = 200704;         // 2048 ints
constexpr int SU_OFF  = 208896;         // 2 x 128 floats
constexpr int RED_OFF = 209920;         // 4 x 128 floats
constexpr int SMEM_BYTES = 211968;
}

// device scratch (no cudaMalloc allowed)
__device__ float g_Ut[BC * Hn];
__device__ float g_Uc[BC * Hn];
__device__ float g_Vc[BC * Hn];
__device__ float g_thorn[BC * Hn];
__device__ float g_cagg[BC * Hn];
__device__ float g_Bfrag[2 * Hn * Hn];   // tf32 fragment-layout images of W2^T

// ---------------- helpers ----------------
__device__ __forceinline__ uint32_t smem_u32(const void* p) {
    uint32_t a;
    asm("{ .reg .u64 t; cvta.to.shared.u64 t, %1; cvt.u32.u64 %0, t; }"
        : "=r"(a) : "l"(p));
    return a;
}
__device__ __forceinline__ uint32_t f2tf(float f) {
    uint32_t u;
    asm("cvt.rna.tf32.f32 %0, %1;" : "=r"(u) : "f"(f));
    return u;
}
__device__ __forceinline__ void cp16(uint32_t dst, const void* src) {
    asm volatile("cp.async.cg.shared.global [%0], [%1], 16;"
                 :: "r"(dst), "l"(src) : "memory");
}
__device__ __forceinline__ void cp_commit() {
    asm volatile("cp.async.commit_group;" ::: "memory");
}
template <int N>
__device__ __forceinline__ void cp_wait() {
    asm volatile("cp.async.wait_group %0;" :: "n"(N) : "memory");
}
__device__ __forceinline__ void mma16818(float* c, uint32_t a0, uint32_t a1,
                                         uint32_t a2, uint32_t a3,
                                         uint32_t b0, uint32_t b1) {
    asm volatile(
        "mma.sync.aligned.m16n8k8.row.col.f32.tf32.tf32.f32 "
        "{%0,%1,%2,%3}, {%4,%5,%6,%7}, {%8,%9}, {%0,%1,%2,%3};"
        : "+f"(c[0]), "+f"(c[1]), "+f"(c[2]), "+f"(c[3])
        : "r"(a0), "r"(a1), "r"(a2), "r"(a3), "r"(b0), "r"(b1));
}

// ---------------------------------------------------------------------------
// Precompute Ut/Uc/Vc: 2048x128 @ 128x128 [+bias].  grid (256,3) x 256 thr.
// ---------------------------------------------------------------------------
__global__ __launch_bounds__(256) void precompute_kernel(
    const float* __restrict__ clone,
    const float* __restrict__ W_thorn, const float* __restrict__ b_thorn,
    const float* __restrict__ W_clone, const float* __restrict__ b_clone)
{
    const float* W; const float* bias; float* out;
    if (blockIdx.y == 0)      { W = W_thorn;           bias = b_thorn; out = g_Ut; }
    else if (blockIdx.y == 1) { W = W_clone;           bias = b_clone; out = g_Uc; }
    else                      { W = W_clone + Hn * Hn; bias = nullptr; out = g_Vc; }

    __shared__ float sA[8][32];
    __shared__ float sW[32][128];
    const int tid = threadIdx.x;
    const int tx = tid & 31, ty = tid >> 5;
    const int m0 = blockIdx.x * 8;

    float acc[4] = {0.f, 0.f, 0.f, 0.f};
    for (int k0 = 0; k0 < Hn; k0 += 32) {
        sA[ty][tx] = clone[(size_t)(m0 + ty) * Hn + k0 + tx];
        #pragma unroll
        for (int i = 0; i < 4; i++) {
            int f = tid + 256 * i;
            int kk = f >> 5, n = (f & 31) * 4;
            *reinterpret_cast<float4*>(&sW[kk][n]) =
                *reinterpret_cast<const float4*>(W + (size_t)(k0 + kk) * Hn + n);
        }
        __syncthreads();
        #pragma unroll
        for (int kk = 0; kk < 32; kk++) {
            float a = sA[ty][kk];
            float4 w = *reinterpret_cast<const float4*>(&sW[kk][tx * 4]);
            acc[0] = fmaf(a, w.x, acc[0]); acc[1] = fmaf(a, w.y, acc[1]);
            acc[2] = fmaf(a, w.z, acc[2]); acc[3] = fmaf(a, w.w, acc[3]);
        }
        __syncthreads();
    }
    float4 o = {acc[0], acc[1], acc[2], acc[3]};
    if (bias) {
        float4 bb = *reinterpret_cast<const float4*>(bias + tx * 4);
        o.x += bb.x; o.y += bb.y; o.z += bb.z; o.w += bb.w;
    }
    *reinterpret_cast<float4*>(&out[(size_t)(m0 + ty) * Hn + tx * 4]) = o;
}

// ---------------------------------------------------------------------------
// Build tf32 fragment-layout images of B = W2^T for both branches.
// Layout: ((ktile*16 + ntile)*32 + lane)*2 + p  holds W2[k][n] with
//   k = ktile*8 + (lane&3) + 4p,  n = ntile*8 + (lane>>2).
// ---------------------------------------------------------------------------
__global__ __launch_bounds__(256) void build_Bfrag_kernel(
    const float* __restrict__ W_thorn, const float* __restrict__ W_clone)
{
    int idx = blockIdx.x * 256 + threadIdx.x;   // 0..32767
    int seg = idx >> 14;
    int o   = idx & 16383;
    int p     = o & 1;
    int lane  = (o >> 1) & 31;
    int ntile = (o >> 6) & 15;
    int ktile = o >> 10;
    int k = ktile * 8 + (lane & 3) + 4 * p;
    int n = ntile * 8 + (lane >> 2);
    const float* Wsrc = seg ? (W_clone + 2 * Hn * Hn) : (W_thorn + Hn * Hn);
    g_Bfrag[seg * 16384 + o] = __uint_as_float(f2tf(Wsrc[(size_t)k * Hn + n]));
}

// ---------------------------------------------------------------------------
// Persistent tensor branch kernel (mma.sync tf32)
// ---------------------------------------------------------------------------
__device__ __forceinline__ void load_tile(const float* __restrict__ rel,
                                          const float* __restrict__ U,
                                          int tile, int slot, uint32_t sb)
{
    const int tid = threadIdx.x;
    const float* src = rel + (size_t)tile * 16384;
    const uint32_t abase = sb + (slot ? A1_OFF : A0_OFF);
    #pragma unroll
    for (int c = 0; c < 16; c++) {
        int j = tid + 256 * c;
        int row = j >> 5, q = j & 31;
        cp16(abase + row * 528 + q * 16, src + (size_t)j * 4);
    }
    if (tid < 32)
        cp16(sb + SU_OFF + slot * 512 + tid * 16, U + (size_t)tile * 128 + tid * 4);
}

template <bool CLONE>
__device__ __forceinline__ void tile_process(int tile, int slot, char* smem,
                                             float* __restrict__ outp)
{
    const int tid = threadIdx.x, lane = tid & 31, wid = tid >> 5;
    const int wm = wid >> 1, wn = wid & 1;
    const int g = lane >> 2, t = lane & 3;
    const int b = tile >> 7;
    const float* As    = reinterpret_cast<const float*>(smem + (slot ? A1_OFF : A0_OFF));
    const float* sB    = reinterpret_cast<const float*>(smem + B_OFF);
    const int*   smask = reinterpret_cast<const int*>(smem + MSK_OFF);
    const float* su    = reinterpret_cast<const float*>(smem + SU_OFF + slot * 512);
    float*       red   = reinterpret_cast<float*>(smem + RED_OFF);

    float acc[2][8][4];
    #pragma unroll
    for (int mt = 0; mt < 2; mt++)
        #pragma unroll
        for (int nt = 0; nt < 8; nt++)
            #pragma unroll
            for (int j = 0; j < 4; j++) acc[mt][nt][j] = 0.f;

    #pragma unroll 4
    for (int kt = 0; kt < 16; kt++) {
        uint2 bf[8];
        #pragma unroll
        for (int nt = 0; nt < 8; nt++)
            bf[nt] = *reinterpret_cast<const uint2*>(
                sB + (size_t)(((kt * 16) + wn * 8 + nt) * 32 + lane) * 2);
        #pragma unroll
        for (int mt = 0; mt < 2; mt++) {
            const float* ar = As + (wm * 32 + mt * 16 + g) * 132 + kt * 8 + t;
            uint32_t a0 = f2tf(ar[0]);
            uint32_t a2 = f2tf(ar[4]);
            uint32_t a1 = f2tf(ar[8 * 132]);
            uint32_t a3 = f2tf(ar[8 * 132 + 4]);
            #pragma unroll
            for (int nt = 0; nt < 8; nt++)
                mma16818(acc[mt][nt], a0, a1, a2, a3, bf[nt].x, bf[nt].y);
        }
    }

    // fused epilogue: +u (+v), mask*relu, column max over 128 rows
    float cmax[8][2];
    #pragma unroll
    for (int nt = 0; nt < 8; nt++) { cmax[nt][0] = 0.f; cmax[nt][1] = 0.f; }

    const float* vb = CLONE ? (g_Vc + (size_t)b * 16384) : nullptr;
    #pragma unroll
    for (int mt = 0; mt < 2; mt++) {
        int r0 = wm * 32 + mt * 16 + g;
        int m0 = smask[b * 128 + r0];
        int m1 = smask[b * 128 + r0 + 8];
        #pragma unroll
        for (int nt = 0; nt < 8; nt++) {
            int c0 = wn * 64 + nt * 8 + t * 2;
            float2 uu = *reinterpret_cast<const float2*>(su + c0);
            float2 v0 = {0.f, 0.f}, v1 = {0.f, 0.f};
            if (CLONE) {
                v0 = *reinterpret_cast<const float2*>(vb + (size_t)r0 * 128 + c0);
                v1 = *reinterpret_cast<const float2*>(vb + (size_t)(r0 + 8) * 128 + c0);
            }
            float x0 = acc[mt][nt][0] + uu.x + v0.x;
            float x1 = acc[mt][nt][1] + uu.y + v0.y;
            float x2 = acc[mt][nt][2] + uu.x + v1.x;
            float x3 = acc[mt][nt][3] + uu.y + v1.y;
            x0 = m0 ? fmaxf(x0, 0.f) : 0.f;
            x1 = m0 ? fmaxf(x1, 0.f) : 0.f;
            x2 = m1 ? fmaxf(x2, 0.f) : 0.f;
            x3 = m1 ? fmaxf(x3, 0.f) : 0.f;
            cmax[nt][0] = fmaxf(cmax[nt][0], fmaxf(x0, x2));
            cmax[nt][1] = fmaxf(cmax[nt][1], fmaxf(x1, x3));
        }
    }
    #pragma unroll
    for (int nt = 0; nt < 8; nt++)
        #pragma unroll
        for (int j2 = 0; j2 < 2; j2++) {
            float v = cmax[nt][j2];
            v = fmaxf(v, __shfl_xor_sync(0xFFFFFFFFu, v, 4));
            v = fmaxf(v, __shfl_xor_sync(0xFFFFFFFFu, v, 8));
            v = fmaxf(v, __shfl_xor_sync(0xFFFFFFFFu, v, 16));
            cmax[nt][j2] = v;
        }
    if (g == 0) {
        #pragma unroll
        for (int nt = 0; nt < 8; nt++) {
            int c0 = wn * 64 + nt * 8 + t * 2;
            red[wm * 128 + c0]     = cmax[nt][0];
            red[wm * 128 + c0 + 1] = cmax[nt][1];
        }
    }
    __syncthreads();
    if (tid < 128) {
        float m = fmaxf(fmaxf(red[tid], red[128 + tid]),
                        fmaxf(red[256 + tid], red[384 + tid]));
        outp[(size_t)tile * 128 + tid] = m;
    }
}

template <bool CLONE>
__device__ void run_segment(const float* __restrict__ rel,
                            const float* __restrict__ Bimg,
                            const float* __restrict__ U,
                            const int*   __restrict__ maskg,
                            float* __restrict__ outp, char* smem)
{
    const int tid = threadIdx.x;
    const uint32_t sb = smem_u32(smem);

    // B fragment image + segment mask (one group)
    for (int j = tid; j < 4096; j += 256)
        cp16(sb + B_OFF + j * 16, Bimg + (size_t)j * 4);
    for (int j = tid; j < 512; j += 256)
        cp16(sb + MSK_OFF + j * 16, maskg + (size_t)j * 4);
    cp_commit();

    const int i0 = blockIdx.x;
    load_tile(rel, U, i0, 0, sb);
    cp_commit();

    int w = 0;
    for (int i = i0; i < BC; i += NCTA, w ^= 1) {
        int nx = i + NCTA;
        if (nx < BC) {
            load_tile(rel, U, nx, w ^ 1, sb);
            cp_commit();
            cp_wait<1>();
        } else {
            cp_wait<0>();
        }
        __syncthreads();
        tile_process<CLONE>(i, w, smem, outp);
        __syncthreads();
    }
}

__global__ __launch_bounds__(256, 1) void branch_persist_kernel(
    const float* __restrict__ thorn_rel, const float* __restrict__ clone_rel,
    const int* __restrict__ thorn_mask,  const int* __restrict__ clone_mask)
{
    extern __shared__ __align__(16) char smem[];
    run_segment<false>(thorn_rel, g_Bfrag,         g_Ut, thorn_mask, g_thorn, smem);
    __syncthreads();
    run_segment<true >(clone_rel, g_Bfrag + 16384, g_Uc, clone_mask, g_cagg, smem);
}

// ---------------------------------------------------------------------------
// Final: out = clone + relu(concat(clone,food,thorn,cagg) @ W_agg + b)
// ---------------------------------------------------------------------------
__global__ __launch_bounds__(256) void final_kernel(
    const float* __restrict__ clone,
    const float* __restrict__ food,
    const float* __restrict__ W_agg,
    const float* __restrict__ b_agg,
    float* __restrict__ out)
{
    __shared__ float sA[8][32];
    __shared__ float sW[32][128];
    const int tid = threadIdx.x;
    const int tx = tid & 31, ty = tid >> 5;
    const int m0 = blockIdx.x * 8;

    float acc[4] = {0.f, 0.f, 0.f, 0.f};
    for (int k0 = 0; k0 < 4 * Hn; k0 += 32) {
        const float* src;
        int s = k0 >> 7;
        if (s == 0)      src = clone;
        else if (s == 1) src = food;
        else if (s == 2) src = g_thorn;
        else             src = g_cagg;
        sA[ty][tx] = src[(size_t)(m0 + ty) * Hn + (k0 & 127) + tx];
        #pragma unroll
        for (int i = 0; i < 4; i++) {
            int f = tid + 256 * i;
            int kk = f >> 5, n = (f & 31) * 4;
            *reinterpret_cast<float4*>(&sW[kk][n]) =
                *reinterpret_cast<const float4*>(W_agg + (size_t)(k0 + kk) * Hn + n);
        }
        __syncthreads();
        #pragma unroll
        for (int kk = 0; kk < 32; kk++) {
            float a = sA[ty][kk];
            float4 w = *reinterpret_cast<const float4*>(&sW[kk][tx * 4]);
            acc[0] = fmaf(a, w.x, acc[0]); acc[1] = fmaf(a, w.y, acc[1]);
            acc[2] = fmaf(a, w.z, acc[2]); acc[3] = fmaf(a, w.w, acc[3]);
        }
        __syncthreads();
    }
    float4 bb = *reinterpret_cast<const float4*>(b_agg + tx * 4);
    int rw = m0 + ty;
    float4 cl = *reinterpret_cast<const float4*>(clone + (size_t)rw * Hn + tx * 4);
    float4 o;
    o.x = cl.x + fmaxf(acc[0] + bb.x, 0.f);
    o.y = cl.y + fmaxf(acc[1] + bb.y, 0.f);
    o.z = cl.z + fmaxf(acc[2] + bb.z, 0.f);
    o.w = cl.w + fmaxf(acc[3] + bb.w, 0.f);
    *reinterpret_cast<float4*>(&out[(size_t)rw * Hn + tx * 4]) = o;
}

// ---------------------------------------------------------------------------
extern "C" void kernel_launch(void* const* d_in, const int* in_sizes, int n_in,
                              void* d_out, int out_size)
{
    const float* food       = (const float*)d_in[0];
    const float* thorn_rel  = (const float*)d_in[1];
    const float* clone      = (const float*)d_in[2];
    const float* clone_rel  = (const float*)d_in[3];
    const int*   thorn_mask = (const int*)  d_in[4];
    const int*   clone_mask = (const int*)  d_in[5];
    const float* W_thorn    = (const float*)d_in[6];
    const float* b_thorn    = (const float*)d_in[7];
    const float* W_clone    = (const float*)d_in[8];
    const float* b_clone    = (const float*)d_in[9];
    const float* W_agg      = (const float*)d_in[10];
    const float* b_agg      = (const float*)d_in[11];
    float* out = (float*)d_out;

    static bool attr_done = false;
    if (!attr_done) {
        cudaFuncSetAttribute(branch_persist_kernel,
                             cudaFuncAttributeMaxDynamicSharedMemorySize, SMEM_BYTES);
        attr_done = true;
    }

    precompute_kernel<<<dim3(256, 3), 256>>>(clone, W_thorn, b_thorn,
                                             W_clone, b_clone);
    build_Bfrag_kernel<<<128, 256>>>(W_thorn, W_clone);
    branch_persist_kernel<<<NCTA, 256, SMEM_BYTES>>>(thorn_rel, clone_rel,
                                                     thorn_mask, clone_mask);
    final_kernel<<<256, 256>>>(clone, food, W_agg, b_agg, out);
}